// round 10
// baseline (speedup 1.0000x reference)
#include <cuda_runtime.h>
#include <cuda_bf16.h>
#include <cstdint>

// Problem constants (fixed by reference):
//   g: (32, 16, 2048, 3) fp32, ar_phi: (3,3), ar_eta: (3,), ar_c: (3,)
//   P=3, KMAX=5 (11 windings), output: (32,) fp32
#define N_MC      32
#define N_SAMP    16
#define T_LEN     2048
#define TPRIME    2044                   // T - 1 - P
#define ROW_ELEMS (T_LEN * 3)            // 6144 floats
#define ROW_VEC4  (ROW_ELEMS / 4)        // 1536 float4s per row

#define CLUSTER   8                      // CTAs per cluster = per output m
#define SPC       2                      // samples per CTA (8*2 = 16 = N_SAMP)
#define GRID      (N_MC * CLUSTER)       // 256 CTAs, single wave
#define BLOCK     256                    // 2 parallel sample-groups x 128 threads
#define CHUNK     16                     // t-outputs per thread (128*16 = 2048)
#define NLD       15                     // float4 loads (20 angles x 3 dims)

#define PI_F      3.14159265358979323846f
#define TWO_PI_F  6.28318530717958647693f
#define INV_2PI_F 0.15915494309189533577f
#define MAGIC_F   12582912.0f            // 1.5 * 2^23

// Torus logmap, all fma-pipe (magic-number round; |x/2pi| < 2.2 << 2^22).
//   k = rint(x/2pi); wrap = x - 2pi*k
// Matches mod(x+pi,2pi)-pi except exact half-period boundaries (measure zero).
__device__ __forceinline__ float wrapf(float x) {
    float y = fmaf(x, INV_2PI_F, MAGIC_F);
    float k = __fadd_rn(y, -MAGIC_F);
    return fmaf(-k, TWO_PI_F, x);
}

__device__ __forceinline__ uint32_t smem_u32(const void* p) {
    uint32_t a;
    asm("{ .reg .u64 t; cvta.to.shared.u64 t, %1; cvt.u32.u64 %0, t; }"
        : "=r"(a) : "l"(p));
    return a;
}

__global__ __launch_bounds__(BLOCK) __cluster_dims__(CLUSTER, 1, 1)
void arp_cluster_kernel(const float* __restrict__ g,
                        const float* __restrict__ ar_phi,
                        const float* __restrict__ ar_eta,
                        const float* __restrict__ ar_c,
                        float* __restrict__ out) {
    __shared__ float sred[3][BLOCK / 32];
    __shared__ float slots[CLUSTER][3];   // leader CTA collects per-rank sums

    const int tid   = threadIdx.x;
    const int inner = tid & 127;          // position within sample-group
    const int sid   = tid >> 7;           // which of this CTA's 2 samples
    const int m     = blockIdx.x / CLUSTER;
    uint32_t rank;
    asm("mov.u32 %0, %%cluster_ctarank;" : "=r"(rank));

    // Small params (L1-cached broadcast loads).
    float ph[3][3], cc[3];
#pragma unroll
    for (int d = 0; d < 3; d++) {
        ph[d][0] = __ldg(&ar_phi[d * 3 + 0]);
        ph[d][1] = __ldg(&ar_phi[d * 3 + 1]);
        ph[d][2] = __ldg(&ar_phi[d * 3 + 2]);
        cc[d]    = __ldg(&ar_c[d]);
    }

    // ---- One sample-row per thread-group. Front-batched vectorized load:
    // angles t0..t0+19, all 3 dims = 60 floats = 15 consecutive float4s
    // (3*t0 = 48*inner divisible by 4). Single memory exposure, max MLP,
    // halo amortized over 16 outputs (1.25x read amplification).
    const int row   = m * N_SAMP + (int)rank * SPC + sid;
    const int t0    = inner * CHUNK;
    const int base  = 12 * inner;         // (3*t0)/4
    const bool full = (t0 + CHUNK <= TPRIME);   // false only for inner == 127
    const float4* g4 = reinterpret_cast<const float4*>(g)
                     + (size_t)row * ROW_VEC4;
    float f[4 * NLD];
#pragma unroll
    for (int k = 0; k < NLD; k++) {
        int idx = base + k;
        if (idx > ROW_VEC4 - 1) idx = ROW_VEC4 - 1;   // tail clamp (unused data)
        float4 v = __ldg(&g4[idx]);
        f[4 * k + 0] = v.x; f[4 * k + 1] = v.y;
        f[4 * k + 2] = v.z; f[4 * k + 3] = v.w;
    }

    // ---- AR(3) on wrapped first-diffs; each dx computed exactly once.
    float acc[3];
#pragma unroll
    for (int d = 0; d < 3; d++) {
        float dx[CHUNK + 3];
#pragma unroll
        for (int j = 0; j < CHUNK + 3; j++)
            dx[j] = wrapf(f[3 * (j + 1) + d] - f[3 * j + d]);
        float ss = 0.f;
        if (full) {
#pragma unroll
            for (int j = 0; j < CHUNK; j++) {
                float dyv = dx[j + 3] - (ph[d][0] * dx[j + 2]
                                       + ph[d][1] * dx[j + 1]
                                       + ph[d][2] * dx[j]);
                float u = dyv - cc[d];
                ss = fmaf(u, u, ss);
            }
        } else {
#pragma unroll
            for (int j = 0; j < CHUNK; j++) {
                float dyv = dx[j + 3] - (ph[d][0] * dx[j + 2]
                                       + ph[d][1] * dx[j + 1]
                                       + ph[d][2] * dx[j]);
                float u = dyv - cc[d];
                if (t0 + j < TPRIME) ss = fmaf(u, u, ss);
            }
        }
        acc[d] = ss;
    }

    // ---- Warp reduce, then 8-warp fold (both sample-groups sum: same m).
#pragma unroll
    for (int off = 16; off; off >>= 1)
#pragma unroll
        for (int d = 0; d < 3; d++)
            acc[d] += __shfl_xor_sync(0xffffffffu, acc[d], off);

    const int lane = tid & 31;
    const int warp = tid >> 5;
    if (lane == 0)
#pragma unroll
        for (int d = 0; d < 3; d++) sred[d][warp] = acc[d];
    __syncthreads();

    // ---- tid0 pushes this CTA's 3 sums into the LEADER CTA's slots via DSMEM.
    if (tid == 0) {
        float S[3];
#pragma unroll
        for (int d = 0; d < 3; d++) {
            float v = sred[d][0];
#pragma unroll
            for (int w = 1; w < BLOCK / 32; w++) v += sred[d][w];
            S[d] = v;
        }
        uint32_t laddr = smem_u32(&slots[rank][0]);   // same layout in every CTA
        uint32_t raddr;
        asm volatile("mapa.shared::cluster.u32 %0, %1, %2;"
                     : "=r"(raddr) : "r"(laddr), "r"(0u));   // -> leader (rank 0)
#pragma unroll
        for (int d = 0; d < 3; d++)
            asm volatile("st.shared::cluster.f32 [%0], %1;"
                         :: "r"(raddr + 4u * d), "f"(S[d]) : "memory");
    }

    // Cluster barrier: release DSMEM stores, then leader may read.
    asm volatile("barrier.cluster.arrive.aligned;" ::: "memory");
    asm volatile("barrier.cluster.wait.aligned;" ::: "memory");

    // ---- Leader CTA: fold 8 ranks + closed-form winding constant, write out[m].
    //   sum_{k=-5..5} winding log-density collapses (sum k = 0, sum k^2 = 110)
    //   per (t,d) to: -5.5*u^2/var - 220*pi^2/var - 11*log(e) - 5.5*log(2*pi).
    // fp32 throughout: abs error ~1e4 vs tolerance budget ~8.5e7.
    if (rank == 0 && tid == 0) {
        float res = 0.f;
#pragma unroll
        for (int d = 0; d < 3; d++) {
            float Sd = 0.f;
#pragma unroll
            for (int r = 0; r < CLUSTER; r++) Sd += slots[r][d];
            float e   = fabsf(ar_eta[d]);            // scale = sqrt(eta^2)
            float var = e * e;
            float C = -220.f * (PI_F * PI_F) / var - 11.f * logf(e)
                      - 5.5f * logf(TWO_PI_F);
            res += -5.5f * Sd / var + (float)(N_SAMP * TPRIME) * C;
        }
        out[m] = res;
    }
}

extern "C" void kernel_launch(void* const* d_in, const int* in_sizes, int n_in,
                              void* d_out, int out_size) {
    const float* g      = (const float*)d_in[0];
    const float* ar_phi = (const float*)d_in[1];
    const float* ar_eta = (const float*)d_in[2];
    const float* ar_c   = (const float*)d_in[3];
    float* out = (float*)d_out;

    arp_cluster_kernel<<<GRID, BLOCK>>>(g, ar_phi, ar_eta, ar_c, out);
}

// round 11
// speedup vs baseline: 1.0404x; 1.0404x over previous
#include <cuda_runtime.h>
#include <cuda_bf16.h>
#include <cstdint>

// Problem constants (fixed by reference):
//   g: (32, 16, 2048, 3) fp32, ar_phi: (3,3), ar_eta: (3,), ar_c: (3,)
//   P=3, KMAX=5 (11 windings), output: (32,) fp32
#define N_MC      32
#define N_SAMP    16
#define T_LEN     2048
#define TPRIME    2044                   // T - 1 - P
#define ROW_ELEMS (T_LEN * 3)            // 6144 floats
#define ROW_VEC4  (ROW_ELEMS / 4)        // 1536 float4s per row

#define CLUSTER   8                      // CTAs per cluster = per output m
#define GRID      (N_MC * CLUSTER)       // 256 CTAs, single wave
#define BLOCK     512                    // 2 sample-groups x 256 threads (R5 shape)
#define CHUNK     8                      // t-outputs per thread
#define NWARPS    (BLOCK / 32)           // 16

#define PI_F      3.14159265358979323846f
#define TWO_PI_F  6.28318530717958647693f
#define INV_2PI_F 0.15915494309189533577f

// Torus logmap: x - 2*pi*rint(x/2pi). Matches mod(x+pi,2pi)-pi except exact
// half-period boundaries (measure zero in fp32 data).
__device__ __forceinline__ float wrapf(float x) {
    return fmaf(-rintf(x * INV_2PI_F), TWO_PI_F, x);
}

__device__ __forceinline__ uint32_t smem_u32(const void* p) {
    uint32_t a;
    asm("{ .reg .u64 t; cvta.to.shared.u64 t, %1; cvt.u32.u64 %0, t; }"
        : "=r"(a) : "l"(p));
    return a;
}

__global__ __launch_bounds__(BLOCK) __cluster_dims__(CLUSTER, 1, 1)
void arp_cluster_kernel(const float* __restrict__ g,
                        const float* __restrict__ ar_phi,
                        const float* __restrict__ ar_eta,
                        const float* __restrict__ ar_c,
                        float* __restrict__ out) {
    __shared__ float sred[3][NWARPS];
    __shared__ float slots[CLUSTER][3];       // leader collects per-rank sums
    __shared__ alignas(8) unsigned long long mbar_storage;

    const uint32_t mbar = smem_u32(&mbar_storage);
    const int tid   = threadIdx.x;
    const int inner = tid & 255;              // position within sample-group
    const int sid   = tid >> 8;               // which of this CTA's 2 samples
    const int m     = blockIdx.x / CLUSTER;
    uint32_t rank;
    asm("mov.u32 %0, %%cluster_ctarank;" : "=r"(rank));

    // ---- Leader inits its collection mbarrier (7 peer arrivals expected),
    // then EVERY thread arrives on the split cluster barrier. The matching
    // wait happens after compute, by which point the barrier has completed:
    // it returns ~free while publishing the init (acq/rel semantics).
    if (rank == 0 && tid == 0) {
        asm volatile("mbarrier.init.shared.b64 [%0], %1;"
                     :: "r"(mbar), "r"((uint32_t)(CLUSTER - 1)) : "memory");
    }
    asm volatile("barrier.cluster.arrive.aligned;" ::: "memory");

    // Small params (L1-cached broadcast loads).
    float ph[3][3], cc[3];
#pragma unroll
    for (int d = 0; d < 3; d++) {
        ph[d][0] = __ldg(&ar_phi[d * 3 + 0]);
        ph[d][1] = __ldg(&ar_phi[d * 3 + 1]);
        ph[d][2] = __ldg(&ar_phi[d * 3 + 2]);
        cc[d]    = __ldg(&ar_c[d]);
    }

    // ---- One sample-row per thread-group: angles t0..t0+11, all 3 dims
    // = 9 consecutive float4s (3*t0 divisible by 4 since t0 % 8 == 0).
    const int row  = m * N_SAMP + (int)rank * 2 + sid;
    const int t0   = inner * CHUNK;
    const int base = (3 * t0) >> 2;
    const float4* g4 = reinterpret_cast<const float4*>(g)
                     + (size_t)row * ROW_VEC4;
    float f[36];
#pragma unroll
    for (int k = 0; k < 9; k++) {
        int idx = base + k;
        if (idx > ROW_VEC4 - 1) idx = ROW_VEC4 - 1;   // tail clamp (unused data)
        float4 v = __ldg(&g4[idx]);
        f[4 * k + 0] = v.x; f[4 * k + 1] = v.y;
        f[4 * k + 2] = v.z; f[4 * k + 3] = v.w;
    }

    // ---- AR(3) on wrapped first-diffs; each dx computed exactly once.
    float acc[3];
#pragma unroll
    for (int d = 0; d < 3; d++) {
        float dx[CHUNK + 3];
#pragma unroll
        for (int j = 0; j < CHUNK + 3; j++)
            dx[j] = wrapf(f[3 * (j + 1) + d] - f[3 * j + d]);
        float ss = 0.f;
#pragma unroll
        for (int j = 0; j < CHUNK; j++) {
            float dyv = dx[j + 3] - (ph[d][0] * dx[j + 2]
                                   + ph[d][1] * dx[j + 1]
                                   + ph[d][2] * dx[j]);
            float u = dyv - cc[d];
            if (t0 + j < TPRIME) ss = fmaf(u, u, ss);
        }
        acc[d] = ss;
    }

    // ---- Warp reduce, then 16-warp fold (both sample-groups: same m).
#pragma unroll
    for (int off = 16; off; off >>= 1)
#pragma unroll
        for (int d = 0; d < 3; d++)
            acc[d] += __shfl_xor_sync(0xffffffffu, acc[d], off);

    const int lane = tid & 31;
    const int warp = tid >> 5;
    if (lane == 0)
#pragma unroll
        for (int d = 0; d < 3; d++) sred[d][warp] = acc[d];
    __syncthreads();

    // ---- Complete the split cluster barrier (all CTAs arrived at start ->
    // returns immediately; guarantees leader's mbarrier init is visible).
    asm volatile("barrier.cluster.wait.aligned;" ::: "memory");

    if (tid == 0) {
        float S[3];
#pragma unroll
        for (int d = 0; d < 3; d++) {
            float v = sred[d][0];
#pragma unroll
            for (int w = 1; w < NWARPS; w++) v += sred[d][w];
            S[d] = v;
        }

        if (rank != 0) {
            // Push to the leader's slots, then release-arrive on its mbarrier.
            // This CTA then simply exits -- no end-of-kernel cluster sync.
            uint32_t laddr = smem_u32(&slots[rank][0]);
            uint32_t raddr;
            asm volatile("mapa.shared::cluster.u32 %0, %1, %2;"
                         : "=r"(raddr) : "r"(laddr), "r"(0u));
#pragma unroll
            for (int d = 0; d < 3; d++)
                asm volatile("st.shared::cluster.f32 [%0], %1;"
                             :: "r"(raddr + 4u * d), "f"(S[d]) : "memory");
            uint32_t rmbar;
            asm volatile("mapa.shared::cluster.u32 %0, %1, %2;"
                         : "=r"(rmbar) : "r"(mbar), "r"(0u));
            asm volatile("mbarrier.arrive.release.cluster.shared::cluster.b64 _, [%0];"
                         :: "r"(rmbar) : "memory");
        } else {
            // Leader: own contribution locally, wait for 7 peer arrivals.
            slots[0][0] = S[0]; slots[0][1] = S[1]; slots[0][2] = S[2];
            uint32_t done;
            asm volatile(
                "{\n\t.reg .pred p;\n\t"
                "mbarrier.try_wait.parity.acquire.cluster.shared::cta.b64 p, [%1], 0;\n\t"
                "selp.b32 %0, 1, 0, p;\n\t}"
                : "=r"(done) : "r"(mbar) : "memory");
            if (!done) {
                asm volatile(
                    "{\n\t.reg .pred P1;\n\t"
                    "W%=:\n\t"
                    "mbarrier.try_wait.parity.acquire.cluster.shared::cta.b64 P1, [%0], 0, 0x989680;\n\t"
                    "@P1 bra.uni D%=;\n\t"
                    "bra.uni W%=;\n\t"
                    "D%=:\n\t}"
                    :: "r"(mbar) : "memory");
            }

            // Fold 8 ranks + closed-form winding constant, write out[m].
            //   sum_{k=-5..5} collapses (sum k = 0, sum k^2 = 110) per (t,d):
            //   -5.5*u^2/var - 220*pi^2/var - 11*log(e) - 5.5*log(2*pi).
            // fp32 throughout: abs err ~1e4 vs tolerance budget ~8.5e7.
            float res = 0.f;
#pragma unroll
            for (int d = 0; d < 3; d++) {
                float Sd = 0.f;
#pragma unroll
                for (int r = 0; r < CLUSTER; r++) Sd += slots[r][d];
                float e   = fabsf(ar_eta[d]);        // scale = sqrt(eta^2)
                float var = e * e;
                float C = -220.f * (PI_F * PI_F) / var - 11.f * logf(e)
                          - 5.5f * logf(TWO_PI_F);
                res += -5.5f * Sd / var + (float)(N_SAMP * TPRIME) * C;
            }
            out[m] = res;
        }
    }
}

extern "C" void kernel_launch(void* const* d_in, const int* in_sizes, int n_in,
                              void* d_out, int out_size) {
    const float* g      = (const float*)d_in[0];
    const float* ar_phi = (const float*)d_in[1];
    const float* ar_eta = (const float*)d_in[2];
    const float* ar_c   = (const float*)d_in[3];
    float* out = (float*)d_out;

    arp_cluster_kernel<<<GRID, BLOCK>>>(g, ar_phi, ar_eta, ar_c, out);
}

// round 12
// speedup vs baseline: 1.2362x; 1.1882x over previous
#include <cuda_runtime.h>
#include <cuda_bf16.h>
#include <cstdint>

// Problem constants (fixed by reference):
//   g: (32, 16, 2048, 3) fp32, ar_phi: (3,3), ar_eta: (3,), ar_c: (3,)
//   P=3, KMAX=5 (11 windings), output: (32,) fp32
#define N_MC      32
#define N_SAMP    16
#define T_LEN     2048
#define TPRIME    2044                   // T - 1 - P
#define ROW_ELEMS (T_LEN * 3)            // 6144 floats
#define ROW_VEC4  (ROW_ELEMS / 4)        // 1536 float4s per row

#define CLUSTER   8                      // CTAs per cluster = per output m
#define SPC       2                      // samples per CTA (8*2 = 16 = N_SAMP)
#define GRID      (N_MC * CLUSTER)       // 256 CTAs, single wave
#define BLOCK     256
#define CHUNK     8                      // t-outputs per thread per sample

#define PI_F      3.14159265358979323846f
#define TWO_PI_F  6.28318530717958647693f
#define INV_2PI_F 0.15915494309189533577f

// Torus logmap: x - 2*pi*rint(x/2pi). Matches mod(x+pi,2pi)-pi except exact
// half-period boundaries (measure zero in fp32 data).
__device__ __forceinline__ float wrapf(float x) {
    return fmaf(-rintf(x * INV_2PI_F), TWO_PI_F, x);
}

__device__ __forceinline__ uint32_t smem_u32(const void* p) {
    uint32_t a;
    asm("{ .reg .u64 t; cvta.to.shared.u64 t, %1; cvt.u32.u64 %0, t; }"
        : "=r"(a) : "l"(p));
    return a;
}

__global__ __launch_bounds__(BLOCK) __cluster_dims__(CLUSTER, 1, 1)
void arp_cluster_kernel(const float* __restrict__ g,
                        const float* __restrict__ ar_phi,
                        const float* __restrict__ ar_eta,
                        const float* __restrict__ ar_c,
                        float* __restrict__ out) {
    __shared__ float sred[3][BLOCK / 32];
    __shared__ float slots[CLUSTER][3];   // leader CTA collects per-rank sums

    const int tid = threadIdx.x;
    const int m   = blockIdx.x / CLUSTER;
    uint32_t rank;
    asm("mov.u32 %0, %%cluster_ctarank;" : "=r"(rank));

    // Small params (L1-cached broadcast loads).
    float ph[3][3], cc[3];
#pragma unroll
    for (int d = 0; d < 3; d++) {
        ph[d][0] = __ldg(&ar_phi[d * 3 + 0]);
        ph[d][1] = __ldg(&ar_phi[d * 3 + 1]);
        ph[d][2] = __ldg(&ar_phi[d * 3 + 2]);
        cc[d]    = __ldg(&ar_c[d]);
    }

    const int t0   = tid * CHUNK;
    const int base = (3 * t0) >> 2;       // 3*t0 divisible by 4 (t0 % 8 == 0)
    const int row0 = m * N_SAMP + (int)rank * SPC;

    // ---- SINGLE front-batched memory exposure: BOTH sample-rows' 9 float4s
    // issued back-to-back (18 independent LDG.128 in flight per thread)
    // before any compute consumes them. One ~600cyc exposure instead of two.
    const float4* g4a = reinterpret_cast<const float4*>(g)
                      + (size_t)row0 * ROW_VEC4;
    const float4* g4b = g4a + ROW_VEC4;
    float f0[36], f1[36];
#pragma unroll
    for (int k = 0; k < 9; k++) {
        int idx = base + k;
        if (idx > ROW_VEC4 - 1) idx = ROW_VEC4 - 1;   // tail clamp (unused data)
        float4 va = __ldg(&g4a[idx]);
        f0[4 * k + 0] = va.x; f0[4 * k + 1] = va.y;
        f0[4 * k + 2] = va.z; f0[4 * k + 3] = va.w;
    }
#pragma unroll
    for (int k = 0; k < 9; k++) {
        int idx = base + k;
        if (idx > ROW_VEC4 - 1) idx = ROW_VEC4 - 1;
        float4 vb = __ldg(&g4b[idx]);
        f1[4 * k + 0] = vb.x; f1[4 * k + 1] = vb.y;
        f1[4 * k + 2] = vb.z; f1[4 * k + 3] = vb.w;
    }

    // ---- AR(3) on wrapped first-diffs for both samples; each dx once.
    float acc[3] = {0.f, 0.f, 0.f};
#pragma unroll
    for (int s = 0; s < SPC; s++) {
        const float* f = (s == 0) ? f0 : f1;
#pragma unroll
        for (int d = 0; d < 3; d++) {
            float dx[CHUNK + 3];
#pragma unroll
            for (int j = 0; j < CHUNK + 3; j++)
                dx[j] = wrapf(f[3 * (j + 1) + d] - f[3 * j + d]);
            float ss = 0.f;
#pragma unroll
            for (int j = 0; j < CHUNK; j++) {
                float dyv = dx[j + 3] - (ph[d][0] * dx[j + 2]
                                       + ph[d][1] * dx[j + 1]
                                       + ph[d][2] * dx[j]);
                float u = dyv - cc[d];
                if (t0 + j < TPRIME) ss = fmaf(u, u, ss);
            }
            acc[d] += ss;
        }
    }

    // ---- Warp reduce, then 8-warp fold.
#pragma unroll
    for (int off = 16; off; off >>= 1)
#pragma unroll
        for (int d = 0; d < 3; d++)
            acc[d] += __shfl_xor_sync(0xffffffffu, acc[d], off);

    const int lane = tid & 31;
    const int warp = tid >> 5;
    if (lane == 0)
#pragma unroll
        for (int d = 0; d < 3; d++) sred[d][warp] = acc[d];
    __syncthreads();

    // ---- tid0 pushes this CTA's 3 sums into the LEADER CTA's slots via DSMEM.
    if (tid == 0) {
        float S[3];
#pragma unroll
        for (int d = 0; d < 3; d++) {
            float v = sred[d][0];
#pragma unroll
            for (int w = 1; w < BLOCK / 32; w++) v += sred[d][w];
            S[d] = v;
        }
        uint32_t laddr = smem_u32(&slots[rank][0]);   // same layout in every CTA
        uint32_t raddr;
        asm volatile("mapa.shared::cluster.u32 %0, %1, %2;"
                     : "=r"(raddr) : "r"(laddr), "r"(0u));   // -> leader (rank 0)
#pragma unroll
        for (int d = 0; d < 3; d++)
            asm volatile("st.shared::cluster.f32 [%0], %1;"
                         :: "r"(raddr + 4u * d), "f"(S[d]) : "memory");
    }

    // Cluster barrier: release DSMEM stores, then leader may read.
    asm volatile("barrier.cluster.arrive.aligned;" ::: "memory");
    asm volatile("barrier.cluster.wait.aligned;" ::: "memory");

    // ---- Leader CTA: fold 8 ranks + closed-form winding constant, write out[m].
    //   sum_{k=-5..5} winding log-density collapses (sum k = 0, sum k^2 = 110)
    //   per (t,d) to: -5.5*u^2/var - 220*pi^2/var - 11*log(e) - 5.5*log(2*pi).
    // fp32 throughout: abs error ~1e4 vs tolerance budget ~8.5e7.
    if (rank == 0 && tid == 0) {
        float res = 0.f;
#pragma unroll
        for (int d = 0; d < 3; d++) {
            float Sd = 0.f;
#pragma unroll
            for (int r = 0; r < CLUSTER; r++) Sd += slots[r][d];
            float e   = fabsf(ar_eta[d]);            // scale = sqrt(eta^2)
            float var = e * e;
            float C = -220.f * (PI_F * PI_F) / var - 11.f * logf(e)
                      - 5.5f * logf(TWO_PI_F);
            res += -5.5f * Sd / var + (float)(N_SAMP * TPRIME) * C;
        }
        out[m] = res;
    }
}

extern "C" void kernel_launch(void* const* d_in, const int* in_sizes, int n_in,
                              void* d_out, int out_size) {
    const float* g      = (const float*)d_in[0];
    const float* ar_phi = (const float*)d_in[1];
    const float* ar_eta = (const float*)d_in[2];
    const float* ar_c   = (const float*)d_in[3];
    float* out = (float*)d_out;

    arp_cluster_kernel<<<GRID, BLOCK>>>(g, ar_phi, ar_eta, ar_c, out);
}